// round 5
// baseline (speedup 1.0000x reference)
#include <cuda_runtime.h>

#define NCLS  19
#define DIM   256
#define NPIX  4096
#define NBINS 51
#define NW    (NCLS * DIM)   // 4864 (c,d) tasks; grid 1216 x 4 warps exactly

// ---- scratch (no allocations allowed) ----
__device__ int   g_perm[NPIX];
__device__ int   g_off[NCLS + 1];
__device__ int   g_cnt[NCLS];
__device__ float g_clsum2[NCLS * 32];       // spread class partial sums
__device__ int   g_ticket;

__device__ __forceinline__ float wredsum(float v) {
#pragma unroll
    for (int m = 16; m; m >>= 1) v += __shfl_xor_sync(0xffffffffu, v, m);
    return v;
}

__device__ __forceinline__ int wrscan_incl(int v) {   // inclusive +scan over lanes
#pragma unroll
    for (int o = 1; o < 32; o <<= 1) {
        int t = __shfl_up_sync(0xffffffffu, v, o);
        if ((threadIdx.x & 31) >= o) v += t;
    }
    return v;
}

__device__ __forceinline__ float ex2(float x) {
    float e;
    asm("ex2.approx.ftz.f32 %0, %1;" : "=f"(e) : "f"(x));
    return e;
}

// K0: dtype-sniff label (int64 vs int32), atomic-free counting sort by class.
// Thread t owns pixels p_r = t + r*1024, r=0..3.
__global__ void __launch_bounds__(1024) k_prep(const int* __restrict__ lab32) {
    __shared__ int scnt[32][20];   // [warp][class] counts -> excl prefix in-place
    __shared__ int stot[20];
    __shared__ int soff[NCLS + 1];
    int tid  = threadIdx.x;
    int w    = tid >> 5;
    int lane = tid & 31;

    // phase A: words [0,4096) — in-bounds under BOTH dtype interpretations.
    int aw[4];
#pragma unroll
    for (int r = 0; r < 4; r++) aw[r] = lab32[tid + r * 1024];
    // int64 labels (0..18): every odd word is 0. Odd words are exactly the
    // words owned by odd tid (offsets r*1024 are even).
    int any = (tid & 1) ? (aw[0] | aw[1] | aw[2] | aw[3]) : 0;
    int is32 = __syncthreads_or(any);

    // resolve class per owned pixel (phase B load only for int64)
    int cs[4];
#pragma unroll
    for (int r = 0; r < 4; r++) {
        int c = is32 ? aw[r] : lab32[2 * (tid + r * 1024)];
        cs[r] = max(0, min(NCLS - 1, c));
    }

    if (lane < 20) scnt[w][lane] = 0;
    if (tid < NCLS * 32) g_clsum2[tid] = 0.f;
    if (tid == 0) g_ticket = 0;
    __syncwarp();

    // within-warp ranks via match_any + running per-warp per-class counters
    int rs[4];
#pragma unroll
    for (int r = 0; r < 4; r++) {
        int c = cs[r];
        unsigned mask = __match_any_sync(0xffffffffu, c);
        int base = scnt[w][c];
        rs[r] = base + __popc(mask & ((1u << lane) - 1u));
        if (lane == (__ffs(mask) - 1)) scnt[w][c] = base + __popc(mask);
        __syncwarp();
    }
    __syncthreads();

    // cross-warp exclusive prefix per class: warp c (c<19) scans over warps
    if (w < NCLS) {
        int v = scnt[lane][w];
        int inc = wrscan_incl(v);
        scnt[lane][w] = inc - v;           // exclusive
        if (lane == 31) { stot[w] = inc; g_cnt[w] = inc; }
    }
    __syncthreads();
    // class offsets: warp 0 scans the 19 totals
    if (w == 0) {
        int v = (lane < NCLS) ? stot[lane] : 0;
        int inc = wrscan_incl(v);
        if (lane < NCLS) {
            soff[lane] = inc - v;
            g_off[lane] = inc - v;
        }
        if (lane == NCLS - 1) { soff[NCLS] = inc; g_off[NCLS] = inc; }
    }
    __syncthreads();

    // scatter pixel ids
#pragma unroll
    for (int r = 0; r < 4; r++) {
        int c = cs[r];
        g_perm[soff[c] + scnt[w][c] + rs[r]] = tid + r * 1024;
    }
}

// K1 (heavy): one warp per (c,d). Reads feature directly through perm
// (no gather kernel). Fused stats + 51-bin KDE + epilogue + spread atomic +
// last-warp-ticket final reduction. Each block also copies a slice of
// feature -> out+1 afterward (overlaps with other blocks' compute).
__global__ void __launch_bounds__(128) k_main(const float* __restrict__ feature,
                                              float* __restrict__ out, int nf) {
    __shared__ float sh[4][52];
    int wslot = threadIdx.x >> 5;
    int w = blockIdx.x * 4 + wslot;
    int lane = threadIdx.x & 31;
    int c = w >> 8;        // 4864 = 19*256
    int d = w & 255;
    int off = g_off[c];
    int cnt = g_off[c + 1] - off;

    const float LOG2E = 1.4426950408889634f;
    const float* __restrict__ fd = feature + d * NPIX;
    const int* __restrict__ pp = g_perm + off;

    if (cnt > 0) {
        // pass 1: per-class mean/var for this feature dim
        float s1 = 0.f, s2 = 0.f;
        for (int i = lane; i < cnt; i += 32) {
            float f = fd[pp[i]];
            s1 += f;
            s2 = fmaf(f, f, s2);
        }
        s1 = wredsum(s1);
        s2 = wredsum(s2);
        float cm  = (float)cnt;
        float miu = s1 / cm;
        float var = fmaxf(s2 / cm - miu * miu, 1e-12f);

        // vs = var/25 ; base-2 exponent coef: -0.5/vs*log2e = -12.5*log2e/var
        float a_s = -12.5f * LOG2E / var;

        float acc[NBINS];
#pragma unroll
        for (int k = 0; k < NBINS; k++) acc[k] = 0.f;

        // pass 2: KDE (loads are L1-hot from pass 1).
        for (int i = lane; i < cnt; i += 32) {
            float f  = fd[pp[i]];
            float p1 = (-2.f * a_s) * f;
            float p0 = a_s * f * f;
#pragma unroll
            for (int k = 0; k < NBINS; k++) {
                float bk  = -5.f + 0.2f * (float)k;
                float arg = fmaf(a_s, bk * bk, fmaf(p1, bk, p0));
                acc[k] += ex2(arg);
            }
        }

#pragma unroll
        for (int k = 0; k < NBINS; k++) acc[k] = wredsum(acc[k]);

        if (lane == 0) {
#pragma unroll
            for (int k = 0; k < NBINS; k++) sh[wslot][k] = acc[k];
        }
        __syncwarp();

        // epilogue: lane k owns bins k and k+32
        bool hi = lane < (NBINS - 32);
        float sv0 = sh[wslot][lane];
        float sv1 = hi ? sh[wslot][lane + 32] : 0.f;
        float sumS = wredsum(sv0 + sv1);

        float at = -0.5f * LOG2E / var;
        float b0 = fmaf(0.2f, (float)lane, -5.f);
        float b1 = b0 + 6.4f;
        float d0 = b0 - miu, d1 = b1 - miu;
        float g0 = ex2(at * d0 * d0);
        float g1 = hi ? ex2(at * d1 * d1) : 0.f;
        float sumT = wredsum(g0 + g1);

        float invS = 1.f / fmaxf(sumS, 1e-30f);
        float invT = 1.f / fmaxf(sumT, 1e-30f);

        float df0 = sv0 * invS - g0 * invT;
        float df1 = sv1 * invS - g1 * invT;
        float ad0 = fabsf(df0), ad1 = fabsf(df1);
        float l0 = (ad0 < 1.f) ? 0.5f * df0 * df0 : ad0 - 0.5f;
        float l1 = (ad1 < 1.f) ? 0.5f * df1 * df1 : ad1 - 0.5f;
        if (!hi) l1 = 0.f;

        float sl = wredsum(l0 + l1);
        if (lane == 0) atomicAdd(&g_clsum2[c * 32 + (d & 31)], sl);
    }

    // publish, then take a ticket; the last of the NW warps finalizes.
    __threadfence();
    int tk = 0;
    if (lane == 0) tk = atomicAdd(&g_ticket, 1);
    tk = __shfl_sync(0xffffffffu, tk, 0);
    if (tk == NW - 1) {
        float v = 0.f, a = 0.f;
#pragma unroll
        for (int j = 1; j < NCLS; j++) {          // class 0 excluded
            int cj = __ldcg(&g_cnt[j]);
            float x = __ldcg(&g_clsum2[j * 32 + lane]);
            if (cj > 0) { v += x; a += (lane == 0) ? 1.f : 0.f; }
        }
        v = wredsum(v);
        a = wredsum(a);
        if (lane == 0) out[0] = (v * (1.f / 13056.f)) / (a + 1e-12f);
    }

    // output copy tail: out[1..nf] = feature[0..nf) (overlapped across blocks)
    int gt = blockIdx.x * 128 + threadIdx.x;
    for (int j = gt; j < nf; j += NW / 4 * 128)
        out[1 + j] = fd[j - d * NPIX];   // == feature[j]; keep fd base math exact
}

extern "C" void kernel_launch(void* const* d_in, const int* in_sizes, int n_in,
                              void* d_out, int out_size) {
    // Inputs: feature (1048576 f32) and label (4096 px); smaller buffer = label.
    int fi = 0, li = 1;
    if (n_in >= 2 && in_sizes[0] < in_sizes[1]) { fi = 1; li = 0; }
    const float* feature = (const float*)d_in[fi];
    const int*   label   = (const int*)d_in[li];
    float* out = (float*)d_out;

    int nf = out_size - 1;
    int cap = DIM * NPIX;
    if (nf > cap) nf = cap;
    if (nf < 0) nf = 0;

    k_prep<<<1, 1024>>>(label);
    k_main<<<NW / 4, 128>>>(feature, out, nf);
}

// round 6
// speedup vs baseline: 1.0430x; 1.0430x over previous
#include <cuda_runtime.h>

#define NCLS  19
#define DIM   256
#define NPIX  4096
#define NBINS 51
#define NW    (NCLS * DIM)    // 4864 (c,d) tasks
#define NWARP (NW / 2)        // 2432 worker warps, 2 tasks each
#define NBLK  (NWARP / 4)     // 608 blocks -> single wave at 7 blocks/SM

// ---- scratch (no allocations allowed) ----
__device__ int   g_off[NCLS + 1];
__device__ int   g_cnt[NCLS];
__device__ float g_Fs[DIM * NPIX];          // class-sorted, d-major
__device__ float g_clsum2[NCLS * 32];       // spread class partial sums
__device__ int   g_ticket;

__device__ __forceinline__ float wredsum(float v) {
#pragma unroll
    for (int m = 16; m; m >>= 1) v += __shfl_xor_sync(0xffffffffu, v, m);
    return v;
}

__device__ __forceinline__ float ex2(float x) {
    float e;
    asm("ex2.approx.ftz.f32 %0, %1;" : "=f"(e) : "f"(x));
    return e;
}

// K0: per-d gather with block-local counting sort (redundant per block; labels
// are 16KB L2-hot, so the redundancy is free parallelism instead of a serial
// 1-block kernel). perm lives in smem shorts; g_perm eliminated.
__global__ void __launch_bounds__(256) k_gp(const int* __restrict__ lab32,
                                            const float* __restrict__ feature) {
    __shared__ short sperm[NPIX];          // 8KB
    __shared__ int scnt[8][20];            // [warp][class] -> excl prefix
    __shared__ int stot[20];
    __shared__ int soff[20];
    int tid  = threadIdx.x;
    int w    = tid >> 5;
    int lane = tid & 31;

    // words [0,4096): in-bounds under both dtype views of the label buffer.
    int aw[16];
#pragma unroll
    for (int r = 0; r < 16; r++) aw[r] = lab32[tid + r * 256];
    // int64 labels (0..18): all odd words zero; odd words owned by odd tid.
    int any = 0;
    if (tid & 1) {
#pragma unroll
        for (int r = 0; r < 16; r++) any |= aw[r];
    }
    int is32 = __syncthreads_or(any);

    if (lane < 20) scnt[w][lane] = 0;
    __syncwarp();

    int cs[16], rs[16];
#pragma unroll
    for (int r = 0; r < 16; r++) {
        int n = tid + r * 256;
        int c = is32 ? aw[r] : lab32[2 * n];
        c = max(0, min(NCLS - 1, c));
        cs[r] = c;
        unsigned mask = __match_any_sync(0xffffffffu, c);
        int base = scnt[w][c];
        rs[r] = base + __popc(mask & ((1u << lane) - 1u));
        if (lane == (__ffs(mask) - 1)) scnt[w][c] = base + __popc(mask);
        __syncwarp();
    }
    __syncthreads();

    // cross-warp exclusive prefix per class (19 threads, 8 steps each)
    if (tid < NCLS) {
        int run = 0;
#pragma unroll
        for (int w2 = 0; w2 < 8; w2++) {
            int t = scnt[w2][tid];
            scnt[w2][tid] = run;
            run += t;
        }
        stot[tid] = run;
    }
    __syncthreads();
    if (tid == 0) {
        int off = 0;
        for (int c = 0; c < NCLS; c++) { soff[c] = off; off += stot[c]; }
    }
    __syncthreads();

#pragma unroll
    for (int r = 0; r < 16; r++) {
        int c = cs[r];
        sperm[soff[c] + scnt[w][c] + rs[r]] = (short)(tid + r * 256);
    }

    if (blockIdx.x == 0) {
        if (tid < NCLS) { g_cnt[tid] = stot[tid]; g_off[tid] = soff[tid]; }
        if (tid == NCLS) g_off[NCLS] = NPIX;
        if (tid < NCLS * 32) g_clsum2[tid] = 0.f;  // 608 < ... covered by loop:
        for (int i = tid + 256; i < NCLS * 32; i += 256) g_clsum2[i] = 0.f;
        if (tid == 255) g_ticket = 0;
    }
    __syncthreads();

    int d = blockIdx.x;
    const float* __restrict__ src = feature + d * NPIX;
    float* __restrict__ dst = g_Fs + d * NPIX;
    for (int j = tid; j < NPIX; j += 256)
        dst[j] = src[sperm[j]];
}

// K1 (heavy): each warp runs 2 adjacent (c,d) tasks -> 608 blocks, single
// wave, MUFU stays saturated. Fused stats + 51-bin KDE + epilogue + spread
// atomic + last-warp-ticket finalize + overlapped output copy.
__global__ void __launch_bounds__(128) k_main(const float* __restrict__ feature,
                                              float* __restrict__ out, int nf) {
    __shared__ float sh[4][52];
    int wslot = threadIdx.x >> 5;
    int gw = blockIdx.x * 4 + wslot;      // 0..2431
    int lane = threadIdx.x & 31;
    const float LOG2E = 1.4426950408889634f;

#pragma unroll 1
    for (int t = 0; t < 2; t++) {
        int wtask = 2 * gw + t;           // 0..4863
        int c = wtask >> 8;
        int d = wtask & 255;
        int off = g_off[c];
        int cnt = g_off[c + 1] - off;
        if (cnt <= 0) continue;

        const float* __restrict__ fp = g_Fs + d * NPIX + off;

        // pass 1: mean/var
        float s1 = 0.f, s2 = 0.f;
        for (int i = lane; i < cnt; i += 32) {
            float f = fp[i];
            s1 += f;
            s2 = fmaf(f, f, s2);
        }
        s1 = wredsum(s1);
        s2 = wredsum(s2);
        float cm  = (float)cnt;
        float miu = s1 / cm;
        float var = fmaxf(s2 / cm - miu * miu, 1e-12f);

        // vs = var/25 ; base-2 coef: -12.5*log2e/var
        float a_s = -12.5f * LOG2E / var;

        float acc[NBINS];
#pragma unroll
        for (int k = 0; k < NBINS; k++) acc[k] = 0.f;

        // pass 2: KDE (fp is L1-hot from pass 1)
        for (int i = lane; i < cnt; i += 32) {
            float f  = fp[i];
            float p1 = (-2.f * a_s) * f;
            float p0 = a_s * f * f;
#pragma unroll
            for (int k = 0; k < NBINS; k++) {
                float bk  = -5.f + 0.2f * (float)k;
                float arg = fmaf(a_s, bk * bk, fmaf(p1, bk, p0));
                acc[k] += ex2(arg);
            }
        }

#pragma unroll
        for (int k = 0; k < NBINS; k++) acc[k] = wredsum(acc[k]);

        if (lane == 0) {
#pragma unroll
            for (int k = 0; k < NBINS; k++) sh[wslot][k] = acc[k];
        }
        __syncwarp();

        // epilogue: lane k owns bins k and k+32
        bool hi = lane < (NBINS - 32);
        float sv0 = sh[wslot][lane];
        float sv1 = hi ? sh[wslot][lane + 32] : 0.f;
        float sumS = wredsum(sv0 + sv1);

        float at = -0.5f * LOG2E / var;
        float b0 = fmaf(0.2f, (float)lane, -5.f);
        float b1 = b0 + 6.4f;
        float d0 = b0 - miu, d1 = b1 - miu;
        float g0 = ex2(at * d0 * d0);
        float g1 = hi ? ex2(at * d1 * d1) : 0.f;
        float sumT = wredsum(g0 + g1);

        float invS = 1.f / fmaxf(sumS, 1e-30f);
        float invT = 1.f / fmaxf(sumT, 1e-30f);

        float df0 = sv0 * invS - g0 * invT;
        float df1 = sv1 * invS - g1 * invT;
        float ad0 = fabsf(df0), ad1 = fabsf(df1);
        float l0 = (ad0 < 1.f) ? 0.5f * df0 * df0 : ad0 - 0.5f;
        float l1 = (ad1 < 1.f) ? 0.5f * df1 * df1 : ad1 - 0.5f;
        if (!hi) l1 = 0.f;

        float sl = wredsum(l0 + l1);
        if (lane == 0) atomicAdd(&g_clsum2[c * 32 + (d & 31)], sl);
    }

    // publish, then ticket; the last of the NWARP warps finalizes.
    __threadfence();
    int tk = 0;
    if (lane == 0) tk = atomicAdd(&g_ticket, 1);
    tk = __shfl_sync(0xffffffffu, tk, 0);
    if (tk == NWARP - 1) {
        float v = 0.f, a = 0.f;
#pragma unroll
        for (int j = 1; j < NCLS; j++) {          // class 0 excluded
            int cj = __ldcg(&g_cnt[j]);
            float x = __ldcg(&g_clsum2[j * 32 + lane]);
            if (cj > 0) { v += x; a += (lane == 0) ? 1.f : 0.f; }
        }
        v = wredsum(v);
        a = wredsum(a);
        if (lane == 0) out[0] = (v * (1.f / 13056.f)) / (a + 1e-12f);
    }

    // output copy: out[1..nf] = feature[0..nf), overlapped across blocks
    int gt = blockIdx.x * 128 + threadIdx.x;
    for (int j = gt; j < nf; j += NBLK * 128)
        out[1 + j] = feature[j];
}

extern "C" void kernel_launch(void* const* d_in, const int* in_sizes, int n_in,
                              void* d_out, int out_size) {
    // Inputs: feature (1048576 f32) and label (4096 px); smaller buffer = label.
    int fi = 0, li = 1;
    if (n_in >= 2 && in_sizes[0] < in_sizes[1]) { fi = 1; li = 0; }
    const float* feature = (const float*)d_in[fi];
    const int*   label   = (const int*)d_in[li];
    float* out = (float*)d_out;

    int nf = out_size - 1;
    int cap = DIM * NPIX;
    if (nf > cap) nf = cap;
    if (nf < 0) nf = 0;

    k_gp<<<DIM, 256>>>(label, feature);
    k_main<<<NBLK, 128>>>(feature, out, nf);
}